// round 5
// baseline (speedup 1.0000x reference)
#include <cuda_runtime.h>
#include <math.h>

#define Bn 512
#define Kn 512
#define Hn 128
#define NTH 448
#define GRID 128

struct __align__(16) Smem {
  float4 whh_q[8*384*4];   // [(i*384+row)*4+q] = W_hh[row][q*32+i*4 ..+3]  (192KB)
  float4 hq[128];          // [(i*16+s*4+q)] = h[s][q*32+i*4 ..+3]          (2KB)
  float  ahst[384][4];     // ah dot results per (row, sample)              (6KB)
  float  g_r[4][128];
  float  g_z[4][128];
  float  g_xn[4][128];
  float  g_hn[4][128];
  float  lift[4][32];
  float  w_lift[192];
  float  b_lift_s[32];
  float  w_head[5][128];
  float  feat[4][8];
  float  b_head_s[8];
  float  u2y_s[12];
  float  theta_s[4][8];
};

__device__ __forceinline__ void ffma2(unsigned long long &acc,
                                      unsigned long long a,
                                      unsigned long long b){
  asm("fma.rn.f32x2 %0, %1, %2, %3;" : "=l"(acc) : "l"(a), "l"(b), "l"(acc));
}
__device__ __forceinline__ float f2sum(unsigned long long v){
  float lo, hi;
  asm("mov.b64 {%0,%1}, %2;" : "=f"(lo), "=f"(hi) : "l"(v));
  return lo + hi;
}
__device__ __forceinline__ float sigm(float x){ return 1.0f/(1.0f+__expf(-x)); }
__device__ __forceinline__ float tanh_f(float x){
  return 2.0f/(1.0f+__expf(-2.0f*x)) - 1.0f;
}

__device__ __forceinline__ void rhs5(const float y[5], const float th[5], float d[5]){
  float r1 = th[0]*y[0]*y[1];
  float r2 = th[1]*y[2];
  float r3 = th[2]*y[2]*y[3];
  float r4 = th[3]*y[4];
  float r5 = th[4]*y[0];
  d[0] = -r1 - r5;
  d[1] = -r1 + r2;
  d[2] =  r1 - r2 - r3;
  d[3] = -r3 + r4;
  d[4] =  r3 - r4 + r5;
}

__global__ __launch_bounds__(NTH, 1)
void krnn_kernel(const float* __restrict__ y0, const float* __restrict__ u_seq,
    const float* __restrict__ dt_seq, const float* __restrict__ y_seq,
    const float* __restrict__ W_lift, const float* __restrict__ b_lift,
    const float* __restrict__ W_ih, const float* __restrict__ W_hh,
    const float* __restrict__ b_ih, const float* __restrict__ b_hh,
    const float* __restrict__ W_head, const float* __restrict__ b_head,
    const float* __restrict__ u2y, float* __restrict__ out)
{
  extern __shared__ __align__(16) char smraw[];
  Smem* sm = reinterpret_cast<Smem*>(smraw);
  const int tid = threadIdx.x;
  const int b0 = blockIdx.x * 4;

  // ---------- one-time staging ----------
  for (int idx = tid; idx < 384*32; idx += NTH) {
    int row = idx >> 5, c = idx & 31, qq = c >> 3, ii = c & 7;
    sm->whh_q[(ii*384 + row)*4 + qq] = reinterpret_cast<const float4*>(W_hh)[idx];
  }
  for (int idx = tid; idx < 128; idx += NTH) sm->hq[idx] = make_float4(0.f,0.f,0.f,0.f);
  for (int i = tid; i < 192; i += NTH) sm->w_lift[i] = W_lift[i];
  for (int i = tid; i < 32;  i += NTH) sm->b_lift_s[i] = b_lift[i];
  for (int i = tid; i < 640; i += NTH) (&sm->w_head[0][0])[i] = W_head[i];
  if (tid < 5) sm->b_head_s[tid] = b_head[tid];
  if (tid < 9) sm->u2y_s[tid] = u2y[tid];

  const bool isgh = (tid < 384);
  const int rg = tid >> 4, sA = (tid >> 2) & 3, q = tid & 3;   // phase-1 mapping
  const int tt = tid - 384;                                     // tail index

  // W_ih row (phase-2, thread=row) in registers
  ulonglong2 wih2[8];
  {
    int r = isgh ? tid : 0;
    const ulonglong2* w4 = reinterpret_cast<const ulonglong2*>(W_ih) + r*8;
    #pragma unroll
    for (int i = 0; i < 8; i++) wih2[i] = w4[i];
  }
  const float bxv = b_ih[isgh ? tid : 0];
  const float bhv = b_hh[isgh ? tid : 0];

  // tail persistent state (threads tt<4 own sample tt)
  float yst[5] = {0,0,0,0,0};
  float uP0=0.f, uP1=0.f, uP2=0.f, dtP=0.f;
  if (!isgh && tt < 4) {
    yst[0] = y0[(b0+tt)*3+0];
    yst[2] = y0[(b0+tt)*3+1];
    yst[4] = y0[(b0+tt)*3+2];
  }
  __syncthreads();

  float* out_theta = out + (size_t)Bn*Kn*3;

  for (int k = 0; k < Kn; ++k) {
    if (isgh) {
      // ===== phase 1: ah = W_hh . h with (rg, s, q) mapping =====
      ulonglong2 hsv[8];
      const char* hbase = (const char*)(sm->hq + (sA*4 + q));
      #pragma unroll
      for (int i = 0; i < 8; i++)
        hsv[i] = *(const ulonglong2*)(hbase + i*(16*16));
      const char* wbase = (const char*)(sm->whh_q + (rg*4 + q));
      float vred[16];
      #pragma unroll
      for (int rr = 0; rr < 16; rr++) {
        unsigned long long a = 0ull;
        #pragma unroll
        for (int i = 0; i < 8; i++) {
          ulonglong2 wv = *(const ulonglong2*)(wbase + (size_t)(i*1536 + rr*96)*16);
          ffma2(a, wv.x, hsv[i].x);
          ffma2(a, wv.y, hsv[i].y);
        }
        vred[rr] = f2sum(a);
      }
      #pragma unroll
      for (int rr = 0; rr < 16; rr++) {
        float v = vred[rr];
        v += __shfl_xor_sync(0xffffffffu, v, 1);
        v += __shfl_xor_sync(0xffffffffu, v, 2);
        if (q == 0) sm->ahst[rg + 24*rr][sA] = v;
      }
    } else {
      // ===== tail warps: prefetch, head(theta_{k-1}), RK4, feat, lift =====
      float u0n=0.f,u1n=0.f,u2n=0.f,dtn=0.f, yt0=0.f,yt1=0.f,yt2=0.f;
      if (tt < 4) {
        int b = b0 + tt;
        const float* up = u_seq + ((size_t)b*Kn + k)*3;
        u0n = up[0]; u1n = up[1]; u2n = up[2];
        dtn = dt_seq[(size_t)b*Kn + k];
        if (k > 0) {
          const float* yp = y_seq + ((size_t)b*Kn + (k-1))*3;
          yt0 = yp[0]; yt1 = yp[1]; yt2 = yp[2];
        }
      }
      if (k > 0 && tt < 20) {
        int p = tt % 5, s = tt / 5;
        float a0=0.f,a1=0.f,a2=0.f,a3=0.f;
        #pragma unroll
        for (int c = 0; c < 32; c++) {
          float4 wv = reinterpret_cast<const float4*>(sm->w_head[p])[c];
          float4 hv = sm->hq[(c & 7)*16 + s*4 + (c >> 3)];
          a0 = fmaf(wv.x, hv.x, a0); a1 = fmaf(wv.y, hv.y, a1);
          a2 = fmaf(wv.z, hv.z, a2); a3 = fmaf(wv.w, hv.w, a3);
        }
        float a = (a0+a1)+(a2+a3) + sm->b_head_s[p];
        float th = 0.001f + 1.999f * sigm(a);
        sm->theta_s[s][p] = th;
        out_theta[((size_t)(b0+s)*Kn + (k-1))*5 + p] = th;
      }
      asm volatile("bar.sync 1, 64;" ::: "memory");
      if (tt < 4) {
        int s = tt, b = b0 + s;
        if (k > 0) {
          float y[5], th[5];
          #pragma unroll
          for (int j=0;j<5;j++) y[j] = yst[j];
          y[0] += uP0*sm->u2y_s[0] + uP1*sm->u2y_s[3] + uP2*sm->u2y_s[6];
          y[2] += uP0*sm->u2y_s[1] + uP1*sm->u2y_s[4] + uP2*sm->u2y_s[7];
          y[4] += uP0*sm->u2y_s[2] + uP1*sm->u2y_s[5] + uP2*sm->u2y_s[8];
          #pragma unroll
          for (int p=0;p<5;p++) th[p] = sm->theta_s[s][p];
          float k1[5],k2[5],k3[5],k4[5],ytv[5];
          rhs5(y, th, k1);
          #pragma unroll
          for (int j=0;j<5;j++) ytv[j] = fmaf(0.5f*dtP, k1[j], y[j]);
          rhs5(ytv, th, k2);
          #pragma unroll
          for (int j=0;j<5;j++) ytv[j] = fmaf(0.5f*dtP, k2[j], y[j]);
          rhs5(ytv, th, k3);
          #pragma unroll
          for (int j=0;j<5;j++) ytv[j] = fmaf(dtP, k3[j], y[j]);
          rhs5(ytv, th, k4);
          float c6 = dtP*(1.0f/6.0f);
          #pragma unroll
          for (int j=0;j<5;j++){
            float v = y[j] + c6*(k1[j] + 2.0f*k2[j] + 2.0f*k3[j] + k4[j]);
            yst[j] = fmaxf(v, 0.0f);
          }
          float* oy = out + ((size_t)b*Kn + (k-1))*3;
          oy[0]=yst[0]; oy[1]=yst[2]; oy[2]=yst[4];
        }
        sm->feat[s][0]=u0n; sm->feat[s][1]=u1n; sm->feat[s][2]=u2n;
        bool tf = (k > 0) && (k % 50 == 0);
        sm->feat[s][3] = tf ? yt0 : yst[0];
        sm->feat[s][4] = tf ? yt1 : yst[2];
        sm->feat[s][5] = tf ? yt2 : yst[4];
        uP0=u0n; uP1=u1n; uP2=u2n; dtP=dtn;
      }
      asm volatile("bar.sync 1, 64;" ::: "memory");
      #pragma unroll
      for (int e = tt; e < 128; e += 64) {
        int s = e >> 5, l = e & 31;
        float a = sm->b_lift_s[l];
        #pragma unroll
        for (int c = 0; c < 6; c++) a = fmaf(sm->w_lift[l*6+c], sm->feat[s][c], a);
        sm->lift[s][l] = a * sigm(a);
      }
    }
    __syncthreads();   // A: lift + ahst ready

    if (isgh) {
      // ===== phase 2: ax (thread = row) + gates =====
      unsigned long long x0[4], x1[4];
      #pragma unroll
      for (int s=0;s<4;s++){ x0[s]=0ull; x1[s]=0ull; }
      #pragma unroll
      for (int l4 = 0; l4 < 8; l4++){
        #pragma unroll
        for (int s=0;s<4;s++){
          ulonglong2 lv = *(const ulonglong2*)&sm->lift[s][l4*4];
          ffma2(x0[s], wih2[l4].x, lv.x);
          ffma2(x1[s], wih2[l4].y, lv.y);
        }
      }
      float4 av = *reinterpret_cast<const float4*>(&sm->ahst[tid][0]);
      float ahf[4] = {av.x+bhv, av.y+bhv, av.z+bhv, av.w+bhv};
      float axf[4];
      #pragma unroll
      for (int s=0;s<4;s++) axf[s] = f2sum(x0[s]) + f2sum(x1[s]) + bxv;
      int g = tid >> 7, rr = tid & 127;
      if (g == 0) {
        #pragma unroll
        for (int s=0;s<4;s++) sm->g_r[s][rr] = axf[s] + ahf[s];
      } else if (g == 1) {
        #pragma unroll
        for (int s=0;s<4;s++) sm->g_z[s][rr] = axf[s] + ahf[s];
      } else {
        #pragma unroll
        for (int s=0;s<4;s++){ sm->g_xn[s][rr] = axf[s]; sm->g_hn[s][rr] = ahf[s]; }
      }
    }
    __syncthreads();   // B: gates ready

    // ===== GRU h update (all threads, write into hq layout) =====
    #pragma unroll
    for (int e = tid; e < 512; e += NTH) {
      int s = e >> 7, t = e & 127;
      float rgt = sigm(sm->g_r[s][t]);
      float zg  = sigm(sm->g_z[s][t]);
      float nn  = tanh_f(fmaf(rgt, sm->g_hn[s][t], sm->g_xn[s][t]));
      float* hp = reinterpret_cast<float*>(sm->hq);
      int qi = t >> 5, ii = (t >> 2) & 7, ee = t & 3;
      int hidx = (ii*16 + s*4 + qi)*4 + ee;
      hp[hidx] = (1.0f - zg)*nn + zg*hp[hidx];
    }
    __syncthreads();   // C: h_{k+1} published
  }

  // ===== epilogue: theta_{K-1} + RK4 for last step =====
  if (!isgh) {
    if (tt < 20) {
      int p = tt % 5, s = tt / 5;
      float a0=0.f,a1=0.f,a2=0.f,a3=0.f;
      #pragma unroll
      for (int c = 0; c < 32; c++) {
        float4 wv = reinterpret_cast<const float4*>(sm->w_head[p])[c];
        float4 hv = sm->hq[(c & 7)*16 + s*4 + (c >> 3)];
        a0 = fmaf(wv.x, hv.x, a0); a1 = fmaf(wv.y, hv.y, a1);
        a2 = fmaf(wv.z, hv.z, a2); a3 = fmaf(wv.w, hv.w, a3);
      }
      float a = (a0+a1)+(a2+a3) + sm->b_head_s[p];
      float th = 0.001f + 1.999f * sigm(a);
      sm->theta_s[s][p] = th;
      out_theta[((size_t)(b0+s)*Kn + (Kn-1))*5 + p] = th;
    }
    asm volatile("bar.sync 1, 64;" ::: "memory");
    if (tt < 4) {
      int s = tt, b = b0 + s;
      float y[5], th[5];
      #pragma unroll
      for (int j=0;j<5;j++) y[j] = yst[j];
      y[0] += uP0*sm->u2y_s[0] + uP1*sm->u2y_s[3] + uP2*sm->u2y_s[6];
      y[2] += uP0*sm->u2y_s[1] + uP1*sm->u2y_s[4] + uP2*sm->u2y_s[7];
      y[4] += uP0*sm->u2y_s[2] + uP1*sm->u2y_s[5] + uP2*sm->u2y_s[8];
      #pragma unroll
      for (int p=0;p<5;p++) th[p] = sm->theta_s[s][p];
      float k1[5],k2[5],k3[5],k4[5],ytv[5];
      rhs5(y, th, k1);
      #pragma unroll
      for (int j=0;j<5;j++) ytv[j] = fmaf(0.5f*dtP, k1[j], y[j]);
      rhs5(ytv, th, k2);
      #pragma unroll
      for (int j=0;j<5;j++) ytv[j] = fmaf(0.5f*dtP, k2[j], y[j]);
      rhs5(ytv, th, k3);
      #pragma unroll
      for (int j=0;j<5;j++) ytv[j] = fmaf(dtP, k3[j], y[j]);
      rhs5(ytv, th, k4);
      float c6 = dtP*(1.0f/6.0f);
      float* oy = out + ((size_t)b*Kn + (Kn-1))*3;
      float o0 = fmaxf(y[0] + c6*(k1[0]+2.f*k2[0]+2.f*k3[0]+k4[0]), 0.f);
      float o2 = fmaxf(y[2] + c6*(k1[2]+2.f*k2[2]+2.f*k3[2]+k4[2]), 0.f);
      float o4 = fmaxf(y[4] + c6*(k1[4]+2.f*k2[4]+2.f*k3[4]+k4[4]), 0.f);
      oy[0]=o0; oy[1]=o2; oy[2]=o4;
    }
  }
}

extern "C" void kernel_launch(void* const* d_in, const int* in_sizes, int n_in,
                              void* d_out, int out_size) {
  const float* y0     = (const float*)d_in[0];
  const float* u_seq  = (const float*)d_in[1];
  const float* dt_seq = (const float*)d_in[2];
  const float* y_seq  = (const float*)d_in[3];
  const float* W_lift = (const float*)d_in[4];
  const float* b_lift = (const float*)d_in[5];
  const float* W_ih   = (const float*)d_in[6];
  const float* W_hh   = (const float*)d_in[7];
  const float* b_ih   = (const float*)d_in[8];
  const float* b_hh   = (const float*)d_in[9];
  const float* W_head = (const float*)d_in[10];
  const float* b_head = (const float*)d_in[11];
  const float* u2y    = (const float*)d_in[12];
  float* out = (float*)d_out;

  cudaFuncSetAttribute(krnn_kernel, cudaFuncAttributeMaxDynamicSharedMemorySize,
                       (int)sizeof(Smem));
  krnn_kernel<<<GRID, NTH, sizeof(Smem)>>>(y0, u_seq, dt_seq, y_seq, W_lift, b_lift,
                                           W_ih, W_hh, b_ih, b_hh, W_head, b_head,
                                           u2y, out);
}

// round 6
// speedup vs baseline: 1.3814x; 1.3814x over previous
#include <cuda_runtime.h>
#include <math.h>

#define Bn 512
#define Kn 512
#define Hn 128
#define NTH 384
#define GRID 128

struct __align__(16) Smem {
  float4 whh_v[32*384];    // [j4*384+row] = W_hh[row][4*j4 .. 4*j4+3]   (192KB)
  float4 hq4[128];         // [j4*4+s] = h[s][4*j4 .. 4*j4+3]            (2KB)
  float  ahst[384][4];     // ah dot per (row, sample)                   (6KB)
  float  g_r[4][128];
  float  g_z[4][128];
  float  g_xn[4][128];
  float  g_hn[4][128];
  float  lift[4][32];
  float  w_lift[192];
  float  b_lift_s[32];
  float  w_head[5][128];
  float  feat[4][8];
  float  b_head_s[8];
  float  u2y_s[12];
  float  theta_s[4][8];
};

__device__ __forceinline__ void ffma2(unsigned long long &acc,
                                      unsigned long long a,
                                      unsigned long long b){
  asm("fma.rn.f32x2 %0, %1, %2, %3;" : "=l"(acc) : "l"(a), "l"(b), "l"(acc));
}
__device__ __forceinline__ float f2sum(unsigned long long v){
  float lo, hi;
  asm("mov.b64 {%0,%1}, %2;" : "=f"(lo), "=f"(hi) : "l"(v));
  return lo + hi;
}
__device__ __forceinline__ float sigm(float x){ return 1.0f/(1.0f+__expf(-x)); }
__device__ __forceinline__ float tanh_f(float x){
  return 2.0f/(1.0f+__expf(-2.0f*x)) - 1.0f;
}

__device__ __forceinline__ void rhs5(const float y[5], const float th[5], float d[5]){
  float r1 = th[0]*y[0]*y[1];
  float r2 = th[1]*y[2];
  float r3 = th[2]*y[2]*y[3];
  float r4 = th[3]*y[4];
  float r5 = th[4]*y[0];
  d[0] = -r1 - r5;
  d[1] = -r1 + r2;
  d[2] =  r1 - r2 - r3;
  d[3] = -r3 + r4;
  d[4] =  r3 - r4 + r5;
}

__global__ __launch_bounds__(NTH, 1)
void krnn_kernel(const float* __restrict__ y0, const float* __restrict__ u_seq,
    const float* __restrict__ dt_seq, const float* __restrict__ y_seq,
    const float* __restrict__ W_lift, const float* __restrict__ b_lift,
    const float* __restrict__ W_ih, const float* __restrict__ W_hh,
    const float* __restrict__ b_ih, const float* __restrict__ b_hh,
    const float* __restrict__ W_head, const float* __restrict__ b_head,
    const float* __restrict__ u2y, float* __restrict__ out)
{
  extern __shared__ __align__(16) char smraw[];
  Smem* sm = reinterpret_cast<Smem*>(smraw);
  const int tid = threadIdx.x;
  const int b0 = blockIdx.x * 4;

  // ---------- one-time staging ----------
  for (int i = tid; i < 384*32; i += NTH) {
    int r = i >> 5, j4 = i & 31;
    sm->whh_v[j4*384 + r] = reinterpret_cast<const float4*>(W_hh)[i];
  }
  // W_ih row tid -> registers as f32x2 pairs
  ulonglong2 wih2[8];
  {
    const ulonglong2* w4 = reinterpret_cast<const ulonglong2*>(W_ih) + tid*8;
    #pragma unroll
    for (int i = 0; i < 8; i++) wih2[i] = w4[i];
  }
  const float bxv = b_ih[tid];
  const float bhv = b_hh[tid];
  for (int i = tid; i < 192; i += NTH) sm->w_lift[i] = W_lift[i];
  for (int i = tid; i < 32;  i += NTH) sm->b_lift_s[i] = b_lift[i];
  for (int i = tid; i < 640; i += NTH) (&sm->w_head[0][0])[i] = W_head[i];
  if (tid < 5) sm->b_head_s[tid] = b_head[tid];
  if (tid < 9) sm->u2y_s[tid] = u2y[tid];
  for (int i = tid; i < 128; i += NTH) sm->hq4[i] = make_float4(0.f,0.f,0.f,0.f);

  // phase-1 lane mapping: warp w handles rows {p*96 + w*8 + rr}, sample sP
  const int wArr = tid >> 5;
  const int rrL  = (tid & 31) >> 2;
  const int sP   = tid & 3;

  // y-state + u + dt in registers of threads 0..3 (sample = tid)
  float yst[5] = {0,0,0,0,0};
  float uP0=0.f, uP1=0.f, uP2=0.f, dtP=0.f;
  if (tid < 4) {
    yst[0] = y0[(b0+tid)*3+0];
    yst[2] = y0[(b0+tid)*3+1];
    yst[4] = y0[(b0+tid)*3+2];
  }
  __syncthreads();

  float* out_theta = out + (size_t)Bn*Kn*3;

  for (int k = 0; k <= Kn; ++k) {
    // ======== TAIL (warps 0-4): finish step k-1, prepare step k ========
    if (tid < 160) {
      if (k > 0) {
        // theta_{k-1} = head(h of step k-1)  [20 dots, 8 threads each]
        int pair = tid >> 3, j = tid & 7;
        int s = pair / 5, p = pair - 5*s;
        float a = 0.0f;
        #pragma unroll
        for (int m = 0; m < 16; m++) {
          int c = j + 8*m;          // element index 0..127
          // h[s][c] from hq4 layout: float index (c>>2)*16 + s*4 + (c&3)
          a = fmaf(sm->w_head[p][c],
                   reinterpret_cast<const float*>(sm->hq4)[(c>>2)*16 + s*4 + (c&3)],
                   a);
        }
        a += __shfl_xor_sync(0xffffffffu, a, 4);
        a += __shfl_xor_sync(0xffffffffu, a, 2);
        a += __shfl_xor_sync(0xffffffffu, a, 1);
        if (j == 0) {
          float th = 0.001f + 1.999f * sigm(a + sm->b_head_s[p]);
          sm->theta_s[s][p] = th;
          out_theta[((size_t)(b0+s)*Kn + (k-1))*5 + p] = th;
        }
      }
      asm volatile("bar.sync 1, 160;" ::: "memory");
      if (tid < 4) {
        int s = tid, b = b0 + s;
        if (k > 0) {
          float y[5], th[5];
          #pragma unroll
          for (int j=0;j<5;j++) y[j] = yst[j];
          y[0] += uP0*sm->u2y_s[0] + uP1*sm->u2y_s[3] + uP2*sm->u2y_s[6];
          y[2] += uP0*sm->u2y_s[1] + uP1*sm->u2y_s[4] + uP2*sm->u2y_s[7];
          y[4] += uP0*sm->u2y_s[2] + uP1*sm->u2y_s[5] + uP2*sm->u2y_s[8];
          #pragma unroll
          for (int p=0;p<5;p++) th[p] = sm->theta_s[s][p];
          float k1[5],k2[5],k3[5],k4[5],ytv[5];
          rhs5(y, th, k1);
          #pragma unroll
          for (int j=0;j<5;j++) ytv[j] = fmaf(0.5f*dtP, k1[j], y[j]);
          rhs5(ytv, th, k2);
          #pragma unroll
          for (int j=0;j<5;j++) ytv[j] = fmaf(0.5f*dtP, k2[j], y[j]);
          rhs5(ytv, th, k3);
          #pragma unroll
          for (int j=0;j<5;j++) ytv[j] = fmaf(dtP, k3[j], y[j]);
          rhs5(ytv, th, k4);
          float c6 = dtP*(1.0f/6.0f);
          #pragma unroll
          for (int j=0;j<5;j++){
            float v = y[j] + c6*(k1[j] + 2.0f*k2[j] + 2.0f*k3[j] + k4[j]);
            yst[j] = fmaxf(v, 0.0f);
          }
          float* oy = out + ((size_t)b*Kn + (k-1))*3;
          oy[0]=yst[0]; oy[1]=yst[2]; oy[2]=yst[4];
        }
        if (k < Kn) {
          const float* up = u_seq + ((size_t)b*Kn + k)*3;
          uP0 = up[0]; uP1 = up[1]; uP2 = up[2];
          dtP = dt_seq[(size_t)b*Kn + k];
          sm->feat[s][0]=uP0; sm->feat[s][1]=uP1; sm->feat[s][2]=uP2;
          bool tf = (k > 0) && (k % 50 == 0);
          if (tf) {
            const float* yp = y_seq + ((size_t)b*Kn + (k-1))*3;
            sm->feat[s][3]=yp[0]; sm->feat[s][4]=yp[1]; sm->feat[s][5]=yp[2];
          } else {
            sm->feat[s][3]=yst[0]; sm->feat[s][4]=yst[2]; sm->feat[s][5]=yst[4];
          }
        }
      }
      asm volatile("bar.sync 1, 160;" ::: "memory");
      if (tid < 128 && k < Kn) {
        int s = tid >> 5, l = tid & 31;
        float a = sm->b_lift_s[l];
        #pragma unroll
        for (int c = 0; c < 6; c++) a = fmaf(sm->w_lift[l*6+c], sm->feat[s][c], a);
        sm->lift[s][l] = a * sigm(a);
      }
    }
    if (k == Kn) break;

    // ======== phase 1: ah = W_hh . h, lane = (rr, s), 4 row-passes ========
    {
      unsigned long long acc0=0ull, acc1=0ull, acc2=0ull, acc3=0ull;
      const ulonglong2* hb = reinterpret_cast<const ulonglong2*>(sm->hq4) + sP;
      const ulonglong2* wb = reinterpret_cast<const ulonglong2*>(sm->whh_v) + wArr*8 + rrL;
      #pragma unroll 8
      for (int j4 = 0; j4 < 32; j4++) {
        ulonglong2 hv = hb[j4*4];
        ulonglong2 w0 = wb[j4*384];
        ulonglong2 w1 = wb[j4*384 + 96];
        ulonglong2 w2 = wb[j4*384 + 192];
        ulonglong2 w3 = wb[j4*384 + 288];
        ffma2(acc0, w0.x, hv.x); ffma2(acc0, w0.y, hv.y);
        ffma2(acc1, w1.x, hv.x); ffma2(acc1, w1.y, hv.y);
        ffma2(acc2, w2.x, hv.x); ffma2(acc2, w2.y, hv.y);
        ffma2(acc3, w3.x, hv.x); ffma2(acc3, w3.y, hv.y);
      }
      int rbase = wArr*8 + rrL;
      sm->ahst[rbase      ][sP] = f2sum(acc0);
      sm->ahst[rbase +  96][sP] = f2sum(acc1);
      sm->ahst[rbase + 192][sP] = f2sum(acc2);
      sm->ahst[rbase + 288][sP] = f2sum(acc3);
    }
    __syncthreads();   // A: ahst + lift ready

    // ======== phase 2: ax (thread = row) + gates ========
    {
      unsigned long long x0[4], x1[4];
      #pragma unroll
      for (int s=0;s<4;s++){ x0[s]=0ull; x1[s]=0ull; }
      #pragma unroll
      for (int l4 = 0; l4 < 8; l4++){
        #pragma unroll
        for (int s=0;s<4;s++){
          ulonglong2 lv = *(const ulonglong2*)&sm->lift[s][l4*4];
          ffma2(x0[s], wih2[l4].x, lv.x);
          ffma2(x1[s], wih2[l4].y, lv.y);
        }
      }
      float4 av = *reinterpret_cast<const float4*>(&sm->ahst[tid][0]);
      float ahf[4] = {av.x+bhv, av.y+bhv, av.z+bhv, av.w+bhv};
      float axf[4];
      #pragma unroll
      for (int s=0;s<4;s++) axf[s] = f2sum(x0[s]) + f2sum(x1[s]) + bxv;
      int g = tid >> 7, rr = tid & 127;
      if (g == 0) {
        #pragma unroll
        for (int s=0;s<4;s++) sm->g_r[s][rr] = axf[s] + ahf[s];
      } else if (g == 1) {
        #pragma unroll
        for (int s=0;s<4;s++) sm->g_z[s][rr] = axf[s] + ahf[s];
      } else {
        #pragma unroll
        for (int s=0;s<4;s++){ sm->g_xn[s][rr] = axf[s]; sm->g_hn[s][rr] = ahf[s]; }
      }
    }
    __syncthreads();   // B: gates ready

    // ======== GRU h update (writes hq4 layout) ========
    {
      float* hp = reinterpret_cast<float*>(sm->hq4);
      #pragma unroll
      for (int e = tid; e < 512; e += NTH) {
        int s = e >> 7, t = e & 127;
        float rgt = sigm(sm->g_r[s][t]);
        float zg  = sigm(sm->g_z[s][t]);
        float nn  = tanh_f(fmaf(rgt, sm->g_hn[s][t], sm->g_xn[s][t]));
        int hidx = (t >> 2)*16 + s*4 + (t & 3);
        hp[hidx] = (1.0f - zg)*nn + zg*hp[hidx];
      }
    }
    __syncthreads();   // C: h_{k+1} published
  }
}

extern "C" void kernel_launch(void* const* d_in, const int* in_sizes, int n_in,
                              void* d_out, int out_size) {
  const float* y0     = (const float*)d_in[0];
  const float* u_seq  = (const float*)d_in[1];
  const float* dt_seq = (const float*)d_in[2];
  const float* y_seq  = (const float*)d_in[3];
  const float* W_lift = (const float*)d_in[4];
  const float* b_lift = (const float*)d_in[5];
  const float* W_ih   = (const float*)d_in[6];
  const float* W_hh   = (const float*)d_in[7];
  const float* b_ih   = (const float*)d_in[8];
  const float* b_hh   = (const float*)d_in[9];
  const float* W_head = (const float*)d_in[10];
  const float* b_head = (const float*)d_in[11];
  const float* u2y    = (const float*)d_in[12];
  float* out = (float*)d_out;

  cudaFuncSetAttribute(krnn_kernel, cudaFuncAttributeMaxDynamicSharedMemorySize,
                       (int)sizeof(Smem));
  krnn_kernel<<<GRID, NTH, sizeof(Smem)>>>(y0, u_seq, dt_seq, y_seq, W_lift, b_lift,
                                           W_ih, W_hh, b_ih, b_hh, W_head, b_head,
                                           u2y, out);
}